// round 1
// baseline (speedup 1.0000x reference)
#include <cuda_runtime.h>
#include <cstdint>

// Problem constants
#define CK   512     // C (reduction dim)
#define VDIM 1024    // V
#define MTOT 131072  // N*T*U

// Tiling
#define BM 128
#define BN 128
#define BK 16
#define SSTRIDE 20      // padded smem row stride in 4B words (conflict-free frags)
#define NTHREADS 256
#define KTILES (CK / BK)

__device__ __forceinline__ float fast_tanh(float x) {
    float y;
    asm("tanh.approx.f32 %0, %1;" : "=f"(y) : "f"(x));
    return y;
}

__device__ __forceinline__ uint32_t to_tf32(float x) {
    uint32_t u;
    asm("cvt.rna.tf32.f32 %0, %1;" : "=r"(u) : "f"(x));
    return u;
}

__device__ __forceinline__ void mma_tf32(float* d, const uint32_t* a, const uint32_t* b) {
    asm volatile(
        "mma.sync.aligned.m16n8k8.row.col.f32.tf32.tf32.f32 "
        "{%0,%1,%2,%3}, {%4,%5,%6,%7}, {%8,%9}, {%0,%1,%2,%3};"
        : "+f"(d[0]), "+f"(d[1]), "+f"(d[2]), "+f"(d[3])
        : "r"(a[0]), "r"(a[1]), "r"(a[2]), "r"(a[3]), "r"(b[0]), "r"(b[1]));
}

__device__ __forceinline__ void store_tanh4(uint32_t* dst, float4 e, float4 p) {
    uint4 q;
    q.x = to_tf32(fast_tanh(e.x + p.x));
    q.y = to_tf32(fast_tanh(e.y + p.y));
    q.z = to_tf32(fast_tanh(e.z + p.z));
    q.w = to_tf32(fast_tanh(e.w + p.w));
    *reinterpret_cast<uint4*>(dst) = q;
}

__device__ __forceinline__ void store_w4(uint32_t* dst, float4 w) {
    uint4 q;
    q.x = to_tf32(w.x);
    q.y = to_tf32(w.y);
    q.z = to_tf32(w.z);
    q.w = to_tf32(w.w);
    *reinterpret_cast<uint4*>(dst) = q;
}

__global__ void __launch_bounds__(NTHREADS)
joiner_kernel(const float* __restrict__ enc, const float* __restrict__ pred,
              const float* __restrict__ W, const float* __restrict__ bias,
              float* __restrict__ out)
{
    __shared__ uint32_t As[2][BM * SSTRIDE];
    __shared__ uint32_t Bs[2][BN * SSTRIDE];

    const int tid  = threadIdx.x;
    const int lane = tid & 31;
    const int wid  = tid >> 5;
    const int m0 = blockIdx.x * BM;
    const int n0 = blockIdx.y * BN;

    // warp layout: 2 (M) x 4 (N); warp tile 64x32
    const int warpM = (wid & 1) * 64;
    const int warpN = (wid >> 1) * 32;

    // ---- staging mapping: 512 float4 items per operand, 2 per thread ----
    // item i: row = i>>2 (tile row), c4 = i&3 (float4 within 16-wide k slab)
    const int rA0 = tid >> 2;       // rows rA0 and rA0+64
    const int cA0 = tid & 3;

    // m -> source rows.  m = n*16384 + t*64 + u:
    //   enc row  = m >> 6            (= n*256 + t)
    //   pred row = (m>>14)*64 + (m&63)
    const int mA0 = m0 + rA0;
    const int mA1 = mA0 + 64;
    const float4* encP0 = reinterpret_cast<const float4*>(enc + (size_t)(mA0 >> 6) * CK) + cA0;
    const float4* encP1 = reinterpret_cast<const float4*>(enc + (size_t)(mA1 >> 6) * CK) + cA0;
    const float4* prdP0 = reinterpret_cast<const float4*>(pred + (size_t)(((mA0 >> 14) << 6) | (mA0 & 63)) * CK) + cA0;
    const float4* prdP1 = reinterpret_cast<const float4*>(pred + (size_t)(((mA1 >> 14) << 6) | (mA1 & 63)) * CK) + cA0;
    const float4* wP0   = reinterpret_cast<const float4*>(W + (size_t)(n0 + rA0) * CK) + cA0;
    const float4* wP1   = reinterpret_cast<const float4*>(W + (size_t)(n0 + rA0 + 64) * CK) + cA0;

    const int sOff0 = rA0 * SSTRIDE + cA0 * 4;
    const int sOff1 = (rA0 + 64) * SSTRIDE + cA0 * 4;

    float acc[4][4][4];
    #pragma unroll
    for (int mt = 0; mt < 4; ++mt)
        #pragma unroll
        for (int nt = 0; nt < 4; ++nt)
            #pragma unroll
            for (int i = 0; i < 4; ++i)
                acc[mt][nt][i] = 0.0f;

    // ---- prologue: stage k-tile 0 ----
    {
        float4 e0 = encP0[0], p0 = prdP0[0];
        float4 e1 = encP1[0], p1 = prdP1[0];
        float4 w0 = wP0[0],   w1 = wP1[0];
        store_tanh4(&As[0][sOff0], e0, p0);
        store_tanh4(&As[0][sOff1], e1, p1);
        store_w4(&Bs[0][sOff0], w0);
        store_w4(&Bs[0][sOff1], w1);
    }
    __syncthreads();

    for (int kb = 0; kb < KTILES; ++kb) {
        const int cur = kb & 1;

        // prefetch next k-tile into registers (overlaps with math)
        float4 ne0, np0, ne1, np1, nw0, nw1;
        if (kb + 1 < KTILES) {
            const int off = (kb + 1) * (BK / 4);
            ne0 = encP0[off]; np0 = prdP0[off];
            ne1 = encP1[off]; np1 = prdP1[off];
            nw0 = wP0[off];   nw1 = wP1[off];
        }

        // ---- compute on stage cur: 2 k-steps of 8 ----
        #pragma unroll
        for (int ks = 0; ks < 2; ++ks) {
            const int kk = ks * 8 + (lane & 3);
            uint32_t a[4][4];
            uint32_t b[4][2];
            #pragma unroll
            for (int mt = 0; mt < 4; ++mt) {
                const int r = warpM + mt * 16 + (lane >> 2);
                a[mt][0] = As[cur][r * SSTRIDE + kk];
                a[mt][1] = As[cur][(r + 8) * SSTRIDE + kk];
                a[mt][2] = As[cur][r * SSTRIDE + kk + 4];
                a[mt][3] = As[cur][(r + 8) * SSTRIDE + kk + 4];
            }
            #pragma unroll
            for (int nt = 0; nt < 4; ++nt) {
                const int r = warpN + nt * 8 + (lane >> 2);
                b[nt][0] = Bs[cur][r * SSTRIDE + kk];
                b[nt][1] = Bs[cur][r * SSTRIDE + kk + 4];
            }
            #pragma unroll
            for (int mt = 0; mt < 4; ++mt)
                #pragma unroll
                for (int nt = 0; nt < 4; ++nt)
                    mma_tf32(acc[mt][nt], a[mt], b[nt]);
        }

        // ---- stage next tile into the other buffer ----
        if (kb + 1 < KTILES) {
            const int nxt = cur ^ 1;
            store_tanh4(&As[nxt][sOff0], ne0, np0);
            store_tanh4(&As[nxt][sOff1], ne1, np1);
            store_w4(&Bs[nxt][sOff0], nw0);
            store_w4(&Bs[nxt][sOff1], nw1);
        }
        __syncthreads();
    }

    // ---- epilogue: add bias, write fp32 output ----
    const int gr = lane >> 2;
    const int gc = (lane & 3) * 2;
    #pragma unroll
    for (int mt = 0; mt < 4; ++mt) {
        const int m = m0 + warpM + mt * 16 + gr;
        #pragma unroll
        for (int nt = 0; nt < 4; ++nt) {
            const int n = n0 + warpN + nt * 8 + gc;
            const float2 bb = *reinterpret_cast<const float2*>(bias + n);
            float2 v0, v1;
            v0.x = acc[mt][nt][0] + bb.x;
            v0.y = acc[mt][nt][1] + bb.y;
            v1.x = acc[mt][nt][2] + bb.x;
            v1.y = acc[mt][nt][3] + bb.y;
            *reinterpret_cast<float2*>(out + (size_t)m * VDIM + n)       = v0;
            *reinterpret_cast<float2*>(out + (size_t)(m + 8) * VDIM + n) = v1;
        }
    }
}

extern "C" void kernel_launch(void* const* d_in, const int* in_sizes, int n_in,
                              void* d_out, int out_size) {
    const float* enc  = (const float*)d_in[0];   // (8,256,512)
    const float* pred = (const float*)d_in[1];   // (8,64,512)
    const float* W    = (const float*)d_in[2];   // (1024,512)
    const float* b    = (const float*)d_in[3];   // (1024,)
    float* out = (float*)d_out;                  // (8,256,64,1024)

    dim3 grid(MTOT / BM, VDIM / BN);   // (1024, 8)
    joiner_kernel<<<grid, NTHREADS>>>(enc, pred, W, b, out);
}

// round 3
// speedup vs baseline: 1.1805x; 1.1805x over previous
#include <cuda_runtime.h>
#include <cstdint>

#define CK     512
#define VDIM   1024
#define MTOT   131072
#define BM     128
#define BN     256
#define NTHREADS 256

// ---- tcgen05 stage layout: A[128][32]f32 (16KB) + B[256][32]f32 (32KB) ----
#define A_BYTES 16384
#define STAGE_BYTES 49152
#define SMEM_DYN (2048 + 2 * STAGE_BYTES)
#define NCHUNK 16              // 512 / 32

// idesc: cformat F32(1)@[4:5], a=TF32(2)@[7:9], b=TF32(2)@[10:12], N/8@[17:22], M/16@[24:28]
#define IDESC ((1u << 4) | (2u << 7) | (2u << 10) | ((BN / 8) << 17) | ((BM / 16) << 24))
// SW128 K-major smem descriptor: layout=2, version=1, SBO=64, LBO=1
#define DESC_BASE ((uint64_t(2) << 61) | (uint64_t(1) << 46) | (uint64_t(64) << 32) | (uint64_t(1) << 16))

// Detect a-feature availability per device-compilation pass
#if defined(__CUDA_ARCH__) && (defined(__CUDA_ARCH_FEAT_SM103_ALL) || defined(__CUDA_ARCH_FEAT_SM100_ALL))
#define USE_TCG 1
#define MINB 2
#else
#define USE_TCG 0
#define MINB 1
#endif

__device__ __forceinline__ float fast_tanh(float x) {
    float y; asm("tanh.approx.f32 %0, %1;" : "=f"(y) : "f"(x)); return y;
}
__device__ __forceinline__ uint32_t to_tf32(float x) {
    uint32_t u; asm("cvt.rna.tf32.f32 %0, %1;" : "=r"(u) : "f"(x)); return u;
}
__device__ __forceinline__ uint32_t smem_u32(const void* p) {
    uint32_t a;
    asm("{ .reg .u64 t; cvta.to.shared.u64 t, %1; cvt.u32.u64 %0, t; }" : "=r"(a) : "l"(p));
    return a;
}
__device__ __forceinline__ void sts128(uint32_t addr, uint32_t a, uint32_t b, uint32_t c, uint32_t d) {
    asm volatile("st.shared.v4.b32 [%0], {%1,%2,%3,%4};" :: "r"(addr), "r"(a), "r"(b), "r"(c), "r"(d) : "memory");
}
__device__ __forceinline__ void lds128f(float& a, float& b, float& c, float& d, uint32_t addr) {
    asm volatile("ld.shared.v4.f32 {%0,%1,%2,%3}, [%4];" : "=f"(a), "=f"(b), "=f"(c), "=f"(d) : "r"(addr));
}
__device__ __forceinline__ uint32_t swz(uint32_t off) { return off ^ ((off >> 3) & 0x70); }

#if !USE_TCG
// fallback warp-mma helper (compiled only in non-'a' passes; host pass gets decl only)
__device__ __forceinline__ void mma_tf32(float* d, const uint32_t* a, const uint32_t* b) {
    asm volatile(
        "mma.sync.aligned.m16n8k8.row.col.f32.tf32.tf32.f32 "
        "{%0,%1,%2,%3}, {%4,%5,%6,%7}, {%8,%9}, {%0,%1,%2,%3};"
        : "+f"(d[0]), "+f"(d[1]), "+f"(d[2]), "+f"(d[3])
        : "r"(a[0]), "r"(a[1]), "r"(a[2]), "r"(a[3]), "r"(b[0]), "r"(b[1]));
}
#endif

#if USE_TCG
__device__ __forceinline__ void mma_tf32_ss(uint32_t d_tmem, uint64_t ad, uint64_t bd, uint32_t idesc, uint32_t en) {
    asm volatile(
        "{\n\t.reg .pred p;\n\t"
        "setp.ne.u32 p, %4, 0;\n\t"
        "tcgen05.mma.cta_group::1.kind::tf32 [%0], %1, %2, %3, {%5,%5,%5,%5}, p;\n\t}"
        :: "r"(d_tmem), "l"(ad), "l"(bd), "r"(idesc), "r"(en), "r"(0u) : "memory");
}
__device__ __forceinline__ void mbar_wait(uint32_t mbar, uint32_t parity) {
    uint32_t done;
    asm volatile(
        "{\n\t.reg .pred p;\n\t"
        "mbarrier.try_wait.parity.acquire.cta.shared::cta.b64 p, [%1], %2;\n\t"
        "selp.b32 %0, 1, 0, p;\n\t}"
        : "=r"(done) : "r"(mbar), "r"(parity) : "memory");
    if (!done) {
        asm volatile(
            "{\n\t.reg .pred P1;\n\t"
            "W_%=:\n\t"
            "mbarrier.try_wait.parity.acquire.cta.shared::cta.b64 P1, [%0], %1, 0x989680;\n\t"
            "@P1 bra.uni D_%=;\n\t"
            "bra.uni W_%=;\n\t"
            "D_%=:\n\t}"
            :: "r"(mbar), "r"(parity) : "memory");
    }
}
#endif

__global__ void __launch_bounds__(NTHREADS, MINB)
joiner_kernel(const float* __restrict__ enc, const float* __restrict__ pred,
              const float* __restrict__ W, const float* __restrict__ bias,
              float* __restrict__ out)
{
    extern __shared__ char smem_raw[];
    const int tid  = threadIdx.x;
    const int lane = tid & 31;
    const int wid  = tid >> 5;
    const int m0 = blockIdx.x * BM;
    const int n0 = blockIdx.y * BN;

#if USE_TCG
    // ==================== tcgen05 tf32 path ====================
    uint32_t base = smem_u32(smem_raw);
    uint32_t ctrl = (base + 1023u) & ~1023u;
    const uint32_t mbar[2] = { ctrl + 16, ctrl + 24 };
    const uint32_t stA[2]  = { ctrl + 1024, ctrl + 1024 + STAGE_BYTES };
    const uint32_t stB[2]  = { stA[0] + A_BYTES, stA[1] + A_BYTES };

    if (wid == 0) {
        asm volatile("tcgen05.alloc.cta_group::1.sync.aligned.shared::cta.b32 [%0], %1;"
                     :: "r"(ctrl), "r"(256u) : "memory");
        asm volatile("tcgen05.relinquish_alloc_permit.cta_group::1.sync.aligned;");
    }
    if (tid == 0) {
        asm volatile("mbarrier.init.shared.b64 [%0], 1;" :: "r"(mbar[0]) : "memory");
        asm volatile("mbarrier.init.shared.b64 [%0], 1;" :: "r"(mbar[1]) : "memory");
    }
    __syncthreads();
    uint32_t tmem;
    asm volatile("ld.shared.b32 %0, [%1];" : "=r"(tmem) : "r"(ctrl));

    // staging geometry: c4 = which float4-pair col, rA = base row
    const int c4 = tid >> 6;        // 0..3
    const int rA = tid & 63;        // 0..63
    const int encRow0 = m0 >> 6;
    const int predRow = ((m0 >> 14) << 6) | rA;
    const float4* encP0 = reinterpret_cast<const float4*>(enc + (size_t)encRow0 * CK);
    const float4* encP1 = reinterpret_cast<const float4*>(enc + (size_t)(encRow0 + 1) * CK);
    const float4* prdP  = reinterpret_cast<const float4*>(pred + (size_t)predRow * CK);
    const uint32_t swA00 = swz((uint32_t)(rA * 128 + c4 * 16));
    const uint32_t swA01 = swz((uint32_t)(rA * 128 + (c4 + 4) * 16));
    const uint32_t swA10 = swz((uint32_t)((rA + 64) * 128 + c4 * 16));
    const uint32_t swA11 = swz((uint32_t)((rA + 64) * 128 + (c4 + 4) * 16));
    const float4* wP[4];
    uint32_t swB0[4], swB1[4];
    #pragma unroll
    for (int j = 0; j < 4; ++j) {
        const int rB = rA + j * 64;
        wP[j]  = reinterpret_cast<const float4*>(W + (size_t)(n0 + rB) * CK);
        swB0[j] = swz((uint32_t)(rB * 128 + c4 * 16));
        swB1[j] = swz((uint32_t)(rB * 128 + (c4 + 4) * 16));
    }

    for (int c = 0; c < NCHUNK; ++c) {
        const int s = c & 1;
        if (c >= 2) mbar_wait(mbar[s], (uint32_t)(((c >> 1) - 1) & 1));

        const int kf4 = c * 8;
        // A = tanh(enc + pred) -> tf32
        {
            float4 e00 = encP0[kf4 + c4], e01 = encP0[kf4 + c4 + 4];
            float4 e10 = encP1[kf4 + c4], e11 = encP1[kf4 + c4 + 4];
            float4 p0  = prdP[kf4 + c4],  p1  = prdP[kf4 + c4 + 4];
            sts128(stA[s] + swA00,
                   to_tf32(fast_tanh(e00.x + p0.x)), to_tf32(fast_tanh(e00.y + p0.y)),
                   to_tf32(fast_tanh(e00.z + p0.z)), to_tf32(fast_tanh(e00.w + p0.w)));
            sts128(stA[s] + swA01,
                   to_tf32(fast_tanh(e01.x + p1.x)), to_tf32(fast_tanh(e01.y + p1.y)),
                   to_tf32(fast_tanh(e01.z + p1.z)), to_tf32(fast_tanh(e01.w + p1.w)));
            sts128(stA[s] + swA10,
                   to_tf32(fast_tanh(e10.x + p0.x)), to_tf32(fast_tanh(e10.y + p0.y)),
                   to_tf32(fast_tanh(e10.z + p0.z)), to_tf32(fast_tanh(e10.w + p0.w)));
            sts128(stA[s] + swA11,
                   to_tf32(fast_tanh(e11.x + p1.x)), to_tf32(fast_tanh(e11.y + p1.y)),
                   to_tf32(fast_tanh(e11.z + p1.z)), to_tf32(fast_tanh(e11.w + p1.w)));
        }
        // B = W -> tf32
        #pragma unroll
        for (int j = 0; j < 4; ++j) {
            float4 w0 = wP[j][kf4 + c4], w1 = wP[j][kf4 + c4 + 4];
            sts128(stB[s] + swB0[j], to_tf32(w0.x), to_tf32(w0.y), to_tf32(w0.z), to_tf32(w0.w));
            sts128(stB[s] + swB1[j], to_tf32(w1.x), to_tf32(w1.y), to_tf32(w1.z), to_tf32(w1.w));
        }
        asm volatile("fence.proxy.async.shared::cta;" ::: "memory");
        __syncthreads();

        if (tid == 0) {
            const uint64_t ad = DESC_BASE | ((uint64_t)(stA[s] >> 4) & 0x3FFF);
            const uint64_t bd = DESC_BASE | ((uint64_t)(stB[s] >> 4) & 0x3FFF);
            #pragma unroll
            for (int k = 0; k < 4; ++k)
                mma_tf32_ss(tmem, ad + 2 * k, bd + 2 * k, IDESC, (c > 0 || k > 0) ? 1u : 0u);
            asm volatile(
                "tcgen05.commit.cta_group::1.mbarrier::arrive::one.shared::cluster.b64 [%0];"
                :: "r"(mbar[s]) : "memory");
        }
    }

    mbar_wait(mbar[0], 1u);
    mbar_wait(mbar[1], 1u);
    __syncthreads();
    asm volatile("tcgen05.fence::after_thread_sync;" ::: "memory");

    // epilogue: TMEM -> rotated SMEM patch -> coalesced STG (+bias)
    const int subp = wid & 3;           // TMEM subpartition = row block
    const int cg   = wid >> 2;          // 0..1: column half
    const uint32_t patch = stA[0] + (uint32_t)wid * 4096;   // 32 rows x 128B

    #pragma unroll
    for (int slab = 0; slab < 4; ++slab) {
        const int colb = cg * 128 + slab * 32;
        uint32_t d[32];
        asm volatile(
            "tcgen05.ld.sync.aligned.32x32b.x32.b32 "
            "{%0,%1,%2,%3,%4,%5,%6,%7,%8,%9,%10,%11,%12,%13,%14,%15,"
            "%16,%17,%18,%19,%20,%21,%22,%23,%24,%25,%26,%27,%28,%29,%30,%31}, [%32];"
            : "=r"(d[0]), "=r"(d[1]), "=r"(d[2]), "=r"(d[3]), "=r"(d[4]), "=r"(d[5]), "=r"(d[6]), "=r"(d[7]),
              "=r"(d[8]), "=r"(d[9]), "=r"(d[10]), "=r"(d[11]), "=r"(d[12]), "=r"(d[13]), "=r"(d[14]), "=r"(d[15]),
              "=r"(d[16]), "=r"(d[17]), "=r"(d[18]), "=r"(d[19]), "=r"(d[20]), "=r"(d[21]), "=r"(d[22]), "=r"(d[23]),
              "=r"(d[24]), "=r"(d[25]), "=r"(d[26]), "=r"(d[27]), "=r"(d[28]), "=r"(d[29]), "=r"(d[30]), "=r"(d[31])
            : "r"(tmem + (uint32_t)colb));
        asm volatile("tcgen05.wait::ld.sync.aligned;" ::: "memory");

        // scatter: lane = TMEM row; rotate col groups by 4*(lane&7) for conflict-free st.v4
        #pragma unroll
        for (int r = 0; r < 32; r += 4) {
            const uint32_t cc = (uint32_t)((r + ((lane & 7) << 2)) & 31);
            sts128(patch + (uint32_t)lane * 128 + cc * 4, d[r], d[r + 1], d[r + 2], d[r + 3]);
        }
        __syncwarp();

        // coalesced readout with un-rotation; add bias
        const int cl = (lane & 7) * 4;
        const int n  = n0 + colb + cl;
        const float4 bb = *reinterpret_cast<const float4*>(bias + n);
        #pragma unroll
        for (int p = 0; p < 8; ++p) {
            const int row = p * 4 + (lane >> 3);
            const uint32_t cc = (uint32_t)((cl + ((row & 7) << 2)) & 31);
            float4 v;
            lds128f(v.x, v.y, v.z, v.w, patch + (uint32_t)row * 128 + cc * 4);
            v.x += bb.x; v.y += bb.y; v.z += bb.z; v.w += bb.w;
            *reinterpret_cast<float4*>(out + (size_t)(m0 + subp * 32 + row) * VDIM + n) = v;
        }
        __syncwarp();
    }

    __syncthreads();
    if (wid == 0)
        asm volatile("tcgen05.dealloc.cta_group::1.sync.aligned.b32 %0, %1;" :: "r"(tmem), "r"(256u));

#else
    // ==================== fallback: mma.sync tf32, warp tile 64x64 ====================
    uint32_t* const sw = reinterpret_cast<uint32_t*>(smem_raw);
    uint32_t* const Asb[2] = { sw,          sw + 2560 };   // 128*20 each
    uint32_t* const Bsb[2] = { sw + 5120,   sw + 10240 };  // 256*20 each

    const int warpM2 = (wid & 1) * 64;
    const int warpN2 = (wid >> 1) * 64;

    const int rA0 = tid >> 2;       // 0..63
    const int cA0 = tid & 3;
    const int mA0 = m0 + rA0;
    const int mA1 = mA0 + 64;
    const float4* encQ0 = reinterpret_cast<const float4*>(enc + (size_t)(mA0 >> 6) * CK) + cA0;
    const float4* encQ1 = reinterpret_cast<const float4*>(enc + (size_t)(mA1 >> 6) * CK) + cA0;
    const float4* prdQ  = reinterpret_cast<const float4*>(pred + (size_t)(((mA0 >> 14) << 6) | (mA0 & 63)) * CK) + cA0;
    const float4* wQ[4];
    #pragma unroll
    for (int j = 0; j < 4; ++j)
        wQ[j] = reinterpret_cast<const float4*>(W + (size_t)(n0 + rA0 + j * 64) * CK) + cA0;

    const int aOff0 = rA0 * 20 + cA0 * 4;
    const int aOff1 = (rA0 + 64) * 20 + cA0 * 4;
    int bOff[4];
    #pragma unroll
    for (int j = 0; j < 4; ++j) bOff[j] = (rA0 + j * 64) * 20 + cA0 * 4;

    float acc[4][8][4];
    #pragma unroll
    for (int mt = 0; mt < 4; ++mt)
        #pragma unroll
        for (int nt = 0; nt < 8; ++nt)
            #pragma unroll
            for (int i = 0; i < 4; ++i) acc[mt][nt][i] = 0.0f;

    auto stageA = [&](uint32_t* As, float4 e0, float4 e1, float4 p) {
        uint4 q0, q1;
        q0.x = to_tf32(fast_tanh(e0.x + p.x)); q0.y = to_tf32(fast_tanh(e0.y + p.y));
        q0.z = to_tf32(fast_tanh(e0.z + p.z)); q0.w = to_tf32(fast_tanh(e0.w + p.w));
        q1.x = to_tf32(fast_tanh(e1.x + p.x)); q1.y = to_tf32(fast_tanh(e1.y + p.y));
        q1.z = to_tf32(fast_tanh(e1.z + p.z)); q1.w = to_tf32(fast_tanh(e1.w + p.w));
        *reinterpret_cast<uint4*>(&As[aOff0]) = q0;
        *reinterpret_cast<uint4*>(&As[aOff1]) = q1;
    };
    auto stageB = [&](uint32_t* Bs, const float4* wv) {
        #pragma unroll
        for (int j = 0; j < 4; ++j) {
            uint4 q;
            q.x = to_tf32(wv[j].x); q.y = to_tf32(wv[j].y);
            q.z = to_tf32(wv[j].z); q.w = to_tf32(wv[j].w);
            *reinterpret_cast<uint4*>(&Bs[bOff[j]]) = q;
        }
    };

    {
        float4 e0 = encQ0[0], e1 = encQ1[0], p = prdQ[0];
        float4 wv[4];
        #pragma unroll
        for (int j = 0; j < 4; ++j) wv[j] = wQ[j][0];
        stageA(Asb[0], e0, e1, p);
        stageB(Bsb[0], wv);
    }
    __syncthreads();

    for (int kb = 0; kb < 32; ++kb) {
        const int cur = kb & 1;
        float4 ne0, ne1, np, nw[4];
        if (kb + 1 < 32) {
            const int off = (kb + 1) * 4;
            ne0 = encQ0[off]; ne1 = encQ1[off]; np = prdQ[off];
            #pragma unroll
            for (int j = 0; j < 4; ++j) nw[j] = wQ[j][off];
        }

        const uint32_t* As = Asb[cur];
        const uint32_t* Bs = Bsb[cur];
        #pragma unroll
        for (int ks = 0; ks < 2; ++ks) {
            const int kk = ks * 8 + (lane & 3);
            uint32_t a[4][4];
            uint32_t b[8][2];
            #pragma unroll
            for (int mt = 0; mt < 4; ++mt) {
                const int r = warpM2 + mt * 16 + (lane >> 2);
                a[mt][0] = As[r * 20 + kk];
                a[mt][1] = As[(r + 8) * 20 + kk];
                a[mt][2] = As[r * 20 + kk + 4];
                a[mt][3] = As[(r + 8) * 20 + kk + 4];
            }
            #pragma unroll
            for (int nt = 0; nt < 8; ++nt) {
                const int rn = warpN2 + nt * 8 + (lane >> 2);
                b[nt][0] = Bs[rn * 20 + kk];
                b[nt][1] = Bs[rn * 20 + kk + 4];
            }
            #pragma unroll
            for (int mt = 0; mt < 4; ++mt)
                #pragma unroll
                for (int nt = 0; nt < 8; ++nt)
                    mma_tf32(acc[mt][nt], a[mt], b[nt]);
        }

        if (kb + 1 < 32) {
            const int nxt = cur ^ 1;
            stageA(Asb[nxt], ne0, ne1, np);
            stageB(Bsb[nxt], nw);
        }
        __syncthreads();
    }

    const int gr = lane >> 2;
    const int gc = (lane & 3) * 2;
    #pragma unroll
    for (int mt = 0; mt < 4; ++mt) {
        const int m = m0 + warpM2 + mt * 16 + gr;
        #pragma unroll
        for (int nt = 0; nt < 8; ++nt) {
            const int n = n0 + warpN2 + nt * 8 + gc;
            const float2 bb = *reinterpret_cast<const float2*>(bias + n);
            float2 v0, v1;
            v0.x = acc[mt][nt][0] + bb.x; v0.y = acc[mt][nt][1] + bb.y;
            v1.x = acc[mt][nt][2] + bb.x; v1.y = acc[mt][nt][3] + bb.y;
            *reinterpret_cast<float2*>(out + (size_t)m * VDIM + n)       = v0;
            *reinterpret_cast<float2*>(out + (size_t)(m + 8) * VDIM + n) = v1;
        }
    }
#endif
}

extern "C" void kernel_launch(void* const* d_in, const int* in_sizes, int n_in,
                              void* d_out, int out_size) {
    const float* enc  = (const float*)d_in[0];   // (8,256,512)
    const float* pred = (const float*)d_in[1];   // (8,64,512)
    const float* W    = (const float*)d_in[2];   // (1024,512)
    const float* b    = (const float*)d_in[3];   // (1024,)
    float* out = (float*)d_out;                  // (8,256,64,1024) fp32

    cudaFuncSetAttribute(joiner_kernel, cudaFuncAttributeMaxDynamicSharedMemorySize, SMEM_DYN);
    dim3 grid(MTOT / BM, VDIM / BN);   // (1024, 4)
    joiner_kernel<<<grid, NTHREADS, SMEM_DYN>>>(enc, pred, W, b, out);
}

// round 5
// speedup vs baseline: 2.3661x; 2.0044x over previous
#include <cuda_runtime.h>
#include <cuda_fp16.h>
#include <cstdint>

#define CK     512
#define VDIM   1024
#define MTOT   131072
#define BM     128
#define BN     256
#define BK     64
#define NCHUNK (CK / BK)       // 8
#define NTHREADS 256

#define A_BYTES     16384      // 128 rows x 128B (fp16 k64)
#define STAGE_BYTES 49152      // A 16KB + B 32KB
#define SMEM_DYN    (3 * STAGE_BYTES + 256)

// fp16 scratch: tanh(enc+pred) precomputed once, W converted once.
__device__ __half Ah_g[(size_t)MTOT * CK];   // 128 MB
__device__ __half Wh_g[(size_t)VDIM * CK];   // 1 MB

__device__ __forceinline__ float fast_tanh(float x) {
    float y; asm("tanh.approx.f32 %0, %1;" : "=f"(y) : "f"(x)); return y;
}
__device__ __forceinline__ uint32_t smem_u32(const void* p) {
    uint32_t a;
    asm("{ .reg .u64 t; cvta.to.shared.u64 t, %1; cvt.u32.u64 %0, t; }" : "=r"(a) : "l"(p));
    return a;
}
__device__ __forceinline__ uint32_t swz(uint32_t x) { return x ^ ((x >> 3) & 0x70); }

#define CP16(s, g) asm volatile("cp.async.cg.shared.global [%0], [%1], 16;" :: "r"(s), "l"(g))
#define CPCOMMIT() asm volatile("cp.async.commit_group;" ::: "memory")

// ---------------- prolog kernels ----------------
__global__ void __launch_bounds__(256) conv_w(const float* __restrict__ W) {
    const int i = blockIdx.x * 256 + threadIdx.x;       // 131072 float4s
    const float4 w = reinterpret_cast<const float4*>(W)[i];
    __half2* o = reinterpret_cast<__half2*>(Wh_g);
    o[2 * i]     = __floats2half2_rn(w.x, w.y);
    o[2 * i + 1] = __floats2half2_rn(w.z, w.w);
}

__global__ void __launch_bounds__(128) conv_a(const float* __restrict__ enc,
                                              const float* __restrict__ pred) {
    const int m = blockIdx.x;
    const int t = threadIdx.x;                          // one float4 per thread
    const float4 e = reinterpret_cast<const float4*>(enc  + (size_t)(m >> 6) * CK)[t];
    const float4 p = reinterpret_cast<const float4*>(pred + (size_t)(((m >> 14) << 6) | (m & 63)) * CK)[t];
    __half2 h0 = __floats2half2_rn(fast_tanh(e.x + p.x), fast_tanh(e.y + p.y));
    __half2 h1 = __floats2half2_rn(fast_tanh(e.z + p.z), fast_tanh(e.w + p.w));
    __half2* o = reinterpret_cast<__half2*>(Ah_g + (size_t)m * CK);
    o[2 * t]     = h0;
    o[2 * t + 1] = h1;
}

// ---------------- main GEMM ----------------
__global__ void __launch_bounds__(NTHREADS)
joiner_gemm(const float* __restrict__ bias, float* __restrict__ out)
{
    extern __shared__ char smem_raw[];
    const uint32_t smemBase = (smem_u32(smem_raw) + 127u) & ~127u;

    const int tid  = threadIdx.x;
    const int lane = tid & 31;
    const int wid  = tid >> 5;
    const int m0 = blockIdx.x * BM;
    const int n0 = blockIdx.y * BN;
    const int warpM = (wid & 1) * 64;
    const int warpN = (wid >> 1) * 64;

    float acc[4][8][4];
    #pragma unroll
    for (int mt = 0; mt < 4; ++mt)
        #pragma unroll
        for (int nt = 0; nt < 8; ++nt)
            #pragma unroll
            for (int i = 0; i < 4; ++i) acc[mt][nt][i] = 0.0f;

    const __half* gA0 = Ah_g + (size_t)m0 * CK;
    const __half* gB0 = Wh_g + (size_t)n0 * CK;

    // ---- cp.async stage issue: A 4x16B/thread, B 8x16B/thread ----
    auto issue_stage = [&](int c, int s) {
        const uint32_t sa = smemBase + (uint32_t)s * STAGE_BYTES;
        const uint32_t sb = sa + A_BYTES;
        const __half* gA = gA0 + c * BK;
        const __half* gB = gB0 + c * BK;
        #pragma unroll
        for (int i = 0; i < 4; ++i) {
            const int q = tid + i * 256;
            const int row = q >> 3, c16 = q & 7;
            CP16(sa + swz((uint32_t)(row * 128 + c16 * 16)), gA + (size_t)row * CK + c16 * 8);
        }
        #pragma unroll
        for (int i = 0; i < 8; ++i) {
            const int q = tid + i * 256;
            const int row = q >> 3, c16 = q & 7;
            CP16(sb + swz((uint32_t)(row * 128 + c16 * 16)), gB + (size_t)row * CK + c16 * 8);
        }
        CPCOMMIT();
    };

    auto compute_stage = [&](int s) {
        const uint32_t sa = smemBase + (uint32_t)s * STAGE_BYTES;
        const uint32_t sb = sa + A_BYTES;
        // A: lanes 0-15 -> rows m0..15 (matrices 0,1); lanes 16-31 -> same rows, k-half 1 (matrices 2,3)
        const uint32_t kbAoff = (uint32_t)((lane >> 4) << 4);
        // B (non-trans): lane group j=lane/8 -> matrix j = (n-block j/2, k-half j&1)
        const int jgrp = lane >> 3;
        const int r8   = lane & 7;
        const uint32_t bNoff = (uint32_t)((jgrp >> 1) * 8 + r8);
        const uint32_t bKoff = (uint32_t)((jgrp & 1) * 16);
        #pragma unroll
        for (int k16 = 0; k16 < 4; ++k16) {
            uint32_t a[4][4];
            const uint32_t kbA = (uint32_t)(k16 * 32) + kbAoff;
            #pragma unroll
            for (int mt = 0; mt < 4; ++mt) {
                const uint32_t ad = sa + swz((uint32_t)((warpM + mt * 16 + (lane & 15)) * 128) + kbA);
                asm volatile("ldmatrix.sync.aligned.m8n8.x4.shared.b16 {%0,%1,%2,%3}, [%4];"
                    : "=r"(a[mt][0]), "=r"(a[mt][1]), "=r"(a[mt][2]), "=r"(a[mt][3]) : "r"(ad));
            }
            uint32_t b[8][2];
            const uint32_t kbB = (uint32_t)(k16 * 32) + bKoff;
            #pragma unroll
            for (int np = 0; np < 4; ++np) {
                const uint32_t ad = sb + swz((uint32_t)(warpN + np * 16 + bNoff) * 128u + kbB);
                asm volatile("ldmatrix.sync.aligned.m8n8.x4.shared.b16 {%0,%1,%2,%3}, [%4];"
                    : "=r"(b[2 * np][0]), "=r"(b[2 * np][1]), "=r"(b[2 * np + 1][0]), "=r"(b[2 * np + 1][1])
                    : "r"(ad));
            }
            #pragma unroll
            for (int mt = 0; mt < 4; ++mt)
                #pragma unroll
                for (int nt = 0; nt < 8; ++nt)
                    asm volatile(
                        "mma.sync.aligned.m16n8k16.row.col.f32.f16.f16.f32 "
                        "{%0,%1,%2,%3},{%4,%5,%6,%7},{%8,%9},{%0,%1,%2,%3};"
                        : "+f"(acc[mt][nt][0]), "+f"(acc[mt][nt][1]),
                          "+f"(acc[mt][nt][2]), "+f"(acc[mt][nt][3])
                        : "r"(a[mt][0]), "r"(a[mt][1]), "r"(a[mt][2]), "r"(a[mt][3]),
                          "r"(b[nt][0]), "r"(b[nt][1]));
        }
    };

    issue_stage(0, 0);
    issue_stage(1, 1);

    #pragma unroll 1
    for (int c = 0; c < NCHUNK; ++c) {
        if (c < NCHUNK - 1) asm volatile("cp.async.wait_group 1;" ::: "memory");
        else                asm volatile("cp.async.wait_group 0;" ::: "memory");
        __syncthreads();
        compute_stage(c % 3);
        if (c + 2 < NCHUNK) issue_stage(c + 2, (c + 2) % 3);
    }

    // ---- epilogue: bias + fp32 store ----
    const int gr = lane >> 2;
    const int gc = (lane & 3) * 2;
    #pragma unroll
    for (int mt = 0; mt < 4; ++mt) {
        const int m = m0 + warpM + mt * 16 + gr;
        #pragma unroll
        for (int nt = 0; nt < 8; ++nt) {
            const int n = n0 + warpN + nt * 8 + gc;
            const float2 bb = *reinterpret_cast<const float2*>(bias + n);
            float2 v0, v1;
            v0.x = acc[mt][nt][0] + bb.x; v0.y = acc[mt][nt][1] + bb.y;
            v1.x = acc[mt][nt][2] + bb.x; v1.y = acc[mt][nt][3] + bb.y;
            *reinterpret_cast<float2*>(out + (size_t)m * VDIM + n)       = v0;
            *reinterpret_cast<float2*>(out + (size_t)(m + 8) * VDIM + n) = v1;
        }
    }
}

extern "C" void kernel_launch(void* const* d_in, const int* in_sizes, int n_in,
                              void* d_out, int out_size) {
    const float* enc  = (const float*)d_in[0];   // (8,256,512)
    const float* pred = (const float*)d_in[1];   // (8,64,512)
    const float* W    = (const float*)d_in[2];   // (1024,512)
    const float* b    = (const float*)d_in[3];   // (1024,)
    float* out = (float*)d_out;                  // (8,256,64,1024) fp32

    cudaFuncSetAttribute(joiner_gemm, cudaFuncAttributeMaxDynamicSharedMemorySize, SMEM_DYN);

    conv_w<<<VDIM * CK / 4 / 256, 256>>>(W);              // 512 blocks
    conv_a<<<MTOT, 128>>>(enc, pred);                     // 131072 blocks
    dim3 grid(MTOT / BM, VDIM / BN);                      // (1024, 4)
    joiner_gemm<<<grid, NTHREADS, SMEM_DYN>>>(b, out);
}

// round 6
// speedup vs baseline: 2.5093x; 1.0605x over previous
#include <cuda_runtime.h>
#include <cuda_fp16.h>
#include <cstdint>

#define CK     512
#define VDIM   1024
#define MTOT   131072
#define BM     128
#define BN     256
#define BK     64
#define NCHUNK (CK / BK)       // 8
#define NTHREADS 512

#define A_BYTES     16384      // 128 rows x 128B (fp16 k64)
#define STAGE_BYTES 49152      // A 16KB + B 32KB
#define SMEM_DYN    (3 * STAGE_BYTES + 256)

// fp16 scratch: tanh(enc+pred) precomputed once, W converted once.
__device__ __half Ah_g[(size_t)MTOT * CK];   // 128 MB
__device__ __half Wh_g[(size_t)VDIM * CK];   // 1 MB

__device__ __forceinline__ float fast_tanh(float x) {
    float y; asm("tanh.approx.f32 %0, %1;" : "=f"(y) : "f"(x)); return y;
}
__device__ __forceinline__ uint32_t smem_u32(const void* p) {
    uint32_t a;
    asm("{ .reg .u64 t; cvta.to.shared.u64 t, %1; cvt.u32.u64 %0, t; }" : "=r"(a) : "l"(p));
    return a;
}
__device__ __forceinline__ uint32_t swz(uint32_t x) { return x ^ ((x >> 3) & 0x70); }

#define CP16(s, g) asm volatile("cp.async.cg.shared.global [%0], [%1], 16;" :: "r"(s), "l"(g))
#define CPCOMMIT() asm volatile("cp.async.commit_group;" ::: "memory")

// ---------------- prolog kernels ----------------
__global__ void __launch_bounds__(256) conv_w(const float* __restrict__ W) {
    const int i = blockIdx.x * 256 + threadIdx.x;       // 131072 float4s
    const float4 w = reinterpret_cast<const float4*>(W)[i];
    __half2* o = reinterpret_cast<__half2*>(Wh_g);
    o[2 * i]     = __floats2half2_rn(w.x, w.y);
    o[2 * i + 1] = __floats2half2_rn(w.z, w.w);
}

__global__ void __launch_bounds__(256) conv_a(const float* __restrict__ enc,
                                              const float* __restrict__ pred) {
    const int g = blockIdx.x * 256 + threadIdx.x;       // float4 id, 16.7M total
    const int m = g >> 7;                               // 128 float4 per m-row
    const int t = g & 127;
    const float4 e = reinterpret_cast<const float4*>(enc  + (size_t)(m >> 6) * CK)[t];
    const float4 p = reinterpret_cast<const float4*>(pred + (size_t)(((m >> 14) << 6) | (m & 63)) * CK)[t];
    __half2 h0 = __floats2half2_rn(fast_tanh(e.x + p.x), fast_tanh(e.y + p.y));
    __half2 h1 = __floats2half2_rn(fast_tanh(e.z + p.z), fast_tanh(e.w + p.w));
    __half2* o = reinterpret_cast<__half2*>(Ah_g);
    o[2 * (size_t)g]     = h0;
    o[2 * (size_t)g + 1] = h1;
}

// ---------------- main GEMM ----------------
__global__ void __launch_bounds__(NTHREADS)
joiner_gemm(const float* __restrict__ bias, float* __restrict__ out)
{
    extern __shared__ char smem_raw[];
    const uint32_t smemBase = (smem_u32(smem_raw) + 127u) & ~127u;

    const int tid  = threadIdx.x;
    const int lane = tid & 31;
    const int wid  = tid >> 5;
    const int n0 = blockIdx.x * BN;       // x = n-tile (4) -> A reuse within wave
    const int m0 = blockIdx.y * BM;       // y = m-tile (1024)
    const int warpM = (wid & 3) * 32;     // 4 warp-rows of 32
    const int warpN = (wid >> 2) * 64;    // 4 warp-cols of 64

    float acc[2][8][4];
    #pragma unroll
    for (int mt = 0; mt < 2; ++mt)
        #pragma unroll
        for (int nt = 0; nt < 8; ++nt)
            #pragma unroll
            for (int i = 0; i < 4; ++i) acc[mt][nt][i] = 0.0f;

    const __half* gA0 = Ah_g + (size_t)m0 * CK;
    const __half* gB0 = Wh_g + (size_t)n0 * CK;

    // ---- cp.async stage issue: A 2x16B/thread, B 4x16B/thread (512 thr) ----
    auto issue_stage = [&](int c, int s) {
        const uint32_t sa = smemBase + (uint32_t)s * STAGE_BYTES;
        const uint32_t sb = sa + A_BYTES;
        const __half* gA = gA0 + c * BK;
        const __half* gB = gB0 + c * BK;
        #pragma unroll
        for (int i = 0; i < 2; ++i) {
            const int q = tid + i * 512;
            const int row = q >> 3, c16 = q & 7;
            CP16(sa + swz((uint32_t)(row * 128 + c16 * 16)), gA + (size_t)row * CK + c16 * 8);
        }
        #pragma unroll
        for (int i = 0; i < 4; ++i) {
            const int q = tid + i * 512;
            const int row = q >> 3, c16 = q & 7;
            CP16(sb + swz((uint32_t)(row * 128 + c16 * 16)), gB + (size_t)row * CK + c16 * 8);
        }
        CPCOMMIT();
    };

    auto compute_stage = [&](int s) {
        const uint32_t sa = smemBase + (uint32_t)s * STAGE_BYTES;
        const uint32_t sb = sa + A_BYTES;
        // A: lanes 0-15 -> 16 rows, k-half 0; lanes 16-31 -> same rows, k-half 1
        const uint32_t kbAoff = (uint32_t)((lane >> 4) << 4);
        // B (non-trans): lane group j=lane/8 -> matrix j = (n-block j/2, k-half j&1)
        const int jgrp = lane >> 3;
        const int r8   = lane & 7;
        const uint32_t bNoff = (uint32_t)((jgrp >> 1) * 8 + r8);
        const uint32_t bKoff = (uint32_t)((jgrp & 1) * 16);
        #pragma unroll
        for (int k16 = 0; k16 < 4; ++k16) {
            uint32_t a[2][4];
            const uint32_t kbA = (uint32_t)(k16 * 32) + kbAoff;
            #pragma unroll
            for (int mt = 0; mt < 2; ++mt) {
                const uint32_t ad = sa + swz((uint32_t)((warpM + mt * 16 + (lane & 15)) * 128) + kbA);
                asm volatile("ldmatrix.sync.aligned.m8n8.x4.shared.b16 {%0,%1,%2,%3}, [%4];"
                    : "=r"(a[mt][0]), "=r"(a[mt][1]), "=r"(a[mt][2]), "=r"(a[mt][3]) : "r"(ad));
            }
            uint32_t b[8][2];
            const uint32_t kbB = (uint32_t)(k16 * 32) + bKoff;
            #pragma unroll
            for (int np = 0; np < 4; ++np) {
                const uint32_t ad = sb + swz((uint32_t)(warpN + np * 16 + bNoff) * 128u + kbB);
                asm volatile("ldmatrix.sync.aligned.m8n8.x4.shared.b16 {%0,%1,%2,%3}, [%4];"
                    : "=r"(b[2 * np][0]), "=r"(b[2 * np][1]), "=r"(b[2 * np + 1][0]), "=r"(b[2 * np + 1][1])
                    : "r"(ad));
            }
            #pragma unroll
            for (int mt = 0; mt < 2; ++mt)
                #pragma unroll
                for (int nt = 0; nt < 8; ++nt)
                    asm volatile(
                        "mma.sync.aligned.m16n8k16.row.col.f32.f16.f16.f32 "
                        "{%0,%1,%2,%3},{%4,%5,%6,%7},{%8,%9},{%0,%1,%2,%3};"
                        : "+f"(acc[mt][nt][0]), "+f"(acc[mt][nt][1]),
                          "+f"(acc[mt][nt][2]), "+f"(acc[mt][nt][3])
                        : "r"(a[mt][0]), "r"(a[mt][1]), "r"(a[mt][2]), "r"(a[mt][3]),
                          "r"(b[nt][0]), "r"(b[nt][1]));
        }
    };

    issue_stage(0, 0);
    issue_stage(1, 1);

    #pragma unroll 1
    for (int c = 0; c < NCHUNK; ++c) {
        if (c < NCHUNK - 1) asm volatile("cp.async.wait_group 1;" ::: "memory");
        else                asm volatile("cp.async.wait_group 0;" ::: "memory");
        __syncthreads();
        compute_stage(c % 3);
        if (c + 2 < NCHUNK) issue_stage(c + 2, (c + 2) % 3);
    }

    // ---- epilogue: bias + fp32 store ----
    const int gr = lane >> 2;
    const int gc = (lane & 3) * 2;
    #pragma unroll
    for (int mt = 0; mt < 2; ++mt) {
        const int m = m0 + warpM + mt * 16 + gr;
        #pragma unroll
        for (int nt = 0; nt < 8; ++nt) {
            const int n = n0 + warpN + nt * 8 + gc;
            const float2 bb = *reinterpret_cast<const float2*>(bias + n);
            float2 v0, v1;
            v0.x = acc[mt][nt][0] + bb.x; v0.y = acc[mt][nt][1] + bb.y;
            v1.x = acc[mt][nt][2] + bb.x; v1.y = acc[mt][nt][3] + bb.y;
            *reinterpret_cast<float2*>(out + (size_t)m * VDIM + n)       = v0;
            *reinterpret_cast<float2*>(out + (size_t)(m + 8) * VDIM + n) = v1;
        }
    }
}

extern "C" void kernel_launch(void* const* d_in, const int* in_sizes, int n_in,
                              void* d_out, int out_size) {
    const float* enc  = (const float*)d_in[0];   // (8,256,512)
    const float* pred = (const float*)d_in[1];   // (8,64,512)
    const float* W    = (const float*)d_in[2];   // (1024,512)
    const float* b    = (const float*)d_in[3];   // (1024,)
    float* out = (float*)d_out;                  // (8,256,64,1024) fp32

    cudaFuncSetAttribute(joiner_gemm, cudaFuncAttributeMaxDynamicSharedMemorySize, SMEM_DYN);

    conv_w<<<VDIM * CK / 4 / 256, 256>>>(W);                   // 512 blocks
    conv_a<<<(size_t)MTOT * CK / 4 / 256, 256>>>(enc, pred);   // 65536 blocks
    dim3 grid(VDIM / BN, MTOT / BM);                           // (4, 1024): x=n for A reuse
    joiner_gemm<<<grid, NTHREADS, SMEM_DYN>>>(b, out);
}